// round 4
// baseline (speedup 1.0000x reference)
#include <cuda_runtime.h>
#include <cuda_bf16.h>

// Problem constants
static constexpr int SEQ    = 2048;
static constexpr int DMODEL = 2048;
static constexpr int NHEAD  = 16;
static constexpr int DHEAD  = 128;
static constexpr float EPSV = 1e-5f;

// Scratch (device globals: no allocation allowed)
__device__ float g_h[SEQ * DMODEL];
__device__ float g_q[SEQ * DMODEL];
__device__ float g_k[SEQ * DMODEL];
__device__ float g_v[SEQ * DMODEL];
__device__ float g_attn[SEQ * DMODEL];

typedef unsigned long long ull;

// ---------------- packed f32x2 helpers (sm_100+) ----------------
__device__ __forceinline__ ull pack2(float lo, float hi) {
    ull r; asm("mov.b64 %0, {%1, %2};" : "=l"(r) : "f"(lo), "f"(hi)); return r;
}
__device__ __forceinline__ void unpack2(ull v, float& lo, float& hi) {
    asm("mov.b64 {%0, %1}, %2;" : "=f"(lo), "=f"(hi) : "l"(v));
}
__device__ __forceinline__ ull fma2(ull a, ull b, ull c) {
    ull d; asm("fma.rn.f32x2 %0, %1, %2, %3;" : "=l"(d) : "l"(a), "l"(b), "l"(c));
    return d;
}

// ---------------- RMSNorm ----------------
__global__ __launch_bounds__(256)
void rmsnorm_kernel(const float* __restrict__ x, const float* __restrict__ w,
                    float* __restrict__ h) {
    int row = blockIdx.x;
    const float* xr = x + (size_t)row * DMODEL;
    float s = 0.f;
    for (int i = threadIdx.x; i < DMODEL; i += 256) { float v = xr[i]; s += v * v; }
    s += __shfl_xor_sync(0xffffffffu, s, 16);
    s += __shfl_xor_sync(0xffffffffu, s, 8);
    s += __shfl_xor_sync(0xffffffffu, s, 4);
    s += __shfl_xor_sync(0xffffffffu, s, 2);
    s += __shfl_xor_sync(0xffffffffu, s, 1);
    __shared__ float red[8];
    if ((threadIdx.x & 31) == 0) red[threadIdx.x >> 5] = s;
    __syncthreads();
    if (threadIdx.x < 32) {
        float t = (threadIdx.x < 8) ? red[threadIdx.x] : 0.f;
        t += __shfl_xor_sync(0xffffffffu, t, 4);
        t += __shfl_xor_sync(0xffffffffu, t, 2);
        t += __shfl_xor_sync(0xffffffffu, t, 1);
        if (threadIdx.x == 0) red[0] = t;
    }
    __syncthreads();
    float r = rsqrtf(red[0] / (float)DMODEL + EPSV);
    float* hr = h + (size_t)row * DMODEL;
    for (int i = threadIdx.x; i < DMODEL; i += 256) hr[i] = w[i] * xr[i] * r;
}

// ---------------- SGEMM: C[M,N] = A[M,K] * B[N,K]^T (+ resid) ----------------
// M=N=K=2048. Block 128x128, BK=16, 256 threads, 8x8 per-thread via FFMA2.
static constexpr int GBM = 128;
static constexpr int GBK = 16;
static constexpr int GPAD = 132;  // padded tile row to dodge STS conflicts

#define STASH(SS)                                                                      \
    As[SS][k4 + 0][r0]      = pa0.x; As[SS][k4 + 1][r0]      = pa0.y;                  \
    As[SS][k4 + 2][r0]      = pa0.z; As[SS][k4 + 3][r0]      = pa0.w;                  \
    As[SS][k4 + 0][r0 + 64] = pa1.x; As[SS][k4 + 1][r0 + 64] = pa1.y;                  \
    As[SS][k4 + 2][r0 + 64] = pa1.z; As[SS][k4 + 3][r0 + 64] = pa1.w;                  \
    Bs[SS][k4 + 0][r0]      = pb0.x; Bs[SS][k4 + 1][r0]      = pb0.y;                  \
    Bs[SS][k4 + 2][r0]      = pb0.z; Bs[SS][k4 + 3][r0]      = pb0.w;                  \
    Bs[SS][k4 + 0][r0 + 64] = pb1.x; Bs[SS][k4 + 1][r0 + 64] = pb1.y;                  \
    Bs[SS][k4 + 2][r0 + 64] = pb1.z; Bs[SS][k4 + 3][r0 + 64] = pb1.w;

__global__ __launch_bounds__(256, 1)
void sgemm_nt(const float* __restrict__ A, const float* __restrict__ B,
              float* __restrict__ C, const float* __restrict__ resid) {
    __shared__ __align__(16) float As[2][GBK][GPAD];
    __shared__ __align__(16) float Bs[2][GBK][GPAD];

    const int tid = threadIdx.x;
    const int m0 = blockIdx.y * GBM;
    const int n0 = blockIdx.x * GBM;
    const int ty = tid >> 4;
    const int tx = tid & 15;
    const int r0 = tid >> 2;          // 0..63 (second load covers +64)
    const int k4 = (tid & 3) << 2;    // 0,4,8,12

    float4 pa0, pa1, pb0, pb1;
    pa0 = *(const float4*)&A[(size_t)(m0 + r0)      * DMODEL + k4];
    pa1 = *(const float4*)&A[(size_t)(m0 + r0 + 64) * DMODEL + k4];
    pb0 = *(const float4*)&B[(size_t)(n0 + r0)      * DMODEL + k4];
    pb1 = *(const float4*)&B[(size_t)(n0 + r0 + 64) * DMODEL + k4];

    ull acc[8][4];
#pragma unroll
    for (int i = 0; i < 8; i++)
#pragma unroll
        for (int j = 0; j < 4; j++) acc[i][j] = 0ull;

    STASH(0);
    __syncthreads();

    const int nk = DMODEL / GBK;  // 128
    int s = 0;
    for (int kt = 0; kt < nk; ++kt) {
        if (kt + 1 < nk) {
            const int ko = (kt + 1) * GBK + k4;
            pa0 = *(const float4*)&A[(size_t)(m0 + r0)      * DMODEL + ko];
            pa1 = *(const float4*)&A[(size_t)(m0 + r0 + 64) * DMODEL + ko];
            pb0 = *(const float4*)&B[(size_t)(n0 + r0)      * DMODEL + ko];
            pb1 = *(const float4*)&B[(size_t)(n0 + r0 + 64) * DMODEL + ko];
        }
#pragma unroll
        for (int kk = 0; kk < GBK; ++kk) {
            float4 a0 = *(const float4*)&As[s][kk][ty * 4];
            float4 a1 = *(const float4*)&As[s][kk][64 + ty * 4];
            float4 b0 = *(const float4*)&Bs[s][kk][tx * 4];
            float4 b1 = *(const float4*)&Bs[s][kk][64 + tx * 4];
            ull q0p = pack2(b0.x, b0.y), q1p = pack2(b0.z, b0.w);
            ull q2p = pack2(b1.x, b1.y), q3p = pack2(b1.z, b1.w);
            float av[8] = {a0.x, a0.y, a0.z, a0.w, a1.x, a1.y, a1.z, a1.w};
#pragma unroll
            for (int i = 0; i < 8; ++i) {
                ull ad = pack2(av[i], av[i]);
                acc[i][0] = fma2(ad, q0p, acc[i][0]);
                acc[i][1] = fma2(ad, q1p, acc[i][1]);
                acc[i][2] = fma2(ad, q2p, acc[i][2]);
                acc[i][3] = fma2(ad, q3p, acc[i][3]);
            }
        }
        if (kt + 1 < nk) {
            const int ns = s ^ 1;
            STASH(ns);
        }
        __syncthreads();
        s ^= 1;
    }

#pragma unroll
    for (int i = 0; i < 8; ++i) {
        int row = m0 + ((i < 4) ? (ty * 4 + i) : (64 + ty * 4 + i - 4));
        float c0, c1, c2, c3, c4, c5, c6, c7;
        unpack2(acc[i][0], c0, c1);
        unpack2(acc[i][1], c2, c3);
        unpack2(acc[i][2], c4, c5);
        unpack2(acc[i][3], c6, c7);
        size_t o0 = (size_t)row * DMODEL + n0 + tx * 4;
        size_t o1 = o0 + 64;
        if (resid) {
            float4 ra = *(const float4*)&resid[o0];
            float4 rb = *(const float4*)&resid[o1];
            c0 += ra.x; c1 += ra.y; c2 += ra.z; c3 += ra.w;
            c4 += rb.x; c5 += rb.y; c6 += rb.z; c7 += rb.w;
        }
        float4 w0 = make_float4(c0, c1, c2, c3);
        float4 w1 = make_float4(c4, c5, c6, c7);
        *(float4*)&C[o0] = w0;
        *(float4*)&C[o1] = w1;
    }
}

// ---------------- RoPE (in-place on Q and K; threads own (d, d+64) pairs) ----------------
__global__ __launch_bounds__(256)
void rope_kernel(float* __restrict__ q, float* __restrict__ k,
                 const float* __restrict__ cosb, const float* __restrict__ sinb) {
    int i = blockIdx.x * blockDim.x + threadIdx.x;  // over SEQ*NHEAD*64
    if (i >= SEQ * NHEAD * 64) return;
    int d = i & 63;
    int h = (i >> 6) & (NHEAD - 1);
    int t = i >> 10;
    size_t base = (size_t)t * DMODEL + h * DHEAD;
    float c1 = cosb[t * DHEAD + d];
    float s1 = sinb[t * DHEAD + d];
    float c2 = cosb[t * DHEAD + d + 64];
    float s2 = sinb[t * DHEAD + d + 64];
    float a = q[base + d], b = q[base + d + 64];
    q[base + d]      = a * c1 - b * s1;
    q[base + d + 64] = b * c2 + a * s2;
    a = k[base + d]; b = k[base + d + 64];
    k[base + d]      = a * c1 - b * s1;
    k[base + d + 64] = b * c2 + a * s2;
}

// ---------------- Flash attention (fp32, online softmax) ----------------
// grid (SEQ/64, NHEAD), 256 threads. Tiles: 64 q-rows x 64 k-cols, d=128.
static constexpr int FBM = 64;
static constexpr int FBN = 64;
static constexpr int PSTRIDE = 68;
static constexpr int FLASH_SMEM = (3 * 128 * 64 + 64 * PSTRIDE) * 4;  // 115712 B

__global__ __launch_bounds__(256, 1)
void flash_attn(const float* __restrict__ q, const float* __restrict__ k,
                const float* __restrict__ v, const int* __restrict__ am,
                float* __restrict__ o) {
    extern __shared__ __align__(16) float sm[];
    float* Qs = sm;                // [128][64]  Qs[d][r], pre-scaled
    float* Ks = sm + 128 * 64;     // [128][64]  Ks[d][c]
    float* Vs = sm + 2 * 128 * 64; // [64][128]  Vs[kr][d]
    float* Ps = sm + 3 * 128 * 64; // [64][PSTRIDE]

    const int tid = threadIdx.x;
    const int ty = tid >> 4, tx = tid & 15;
    const int q0 = blockIdx.x * FBM;
    const int hoff = blockIdx.y * DHEAD;
    const float sc = 0.08838834764831845f;  // 1/sqrt(128)

    const int lr  = tid >> 5;         // 0..7
    const int ld4 = (tid & 31) << 2;  // 0..124

#pragma unroll
    for (int j = 0; j < 8; ++j) {
        int row = lr + j * 8;
        float4 qv = *(const float4*)&q[(size_t)(q0 + row) * DMODEL + hoff + ld4];
        Qs[(ld4 + 0) * 64 + row] = qv.x * sc;
        Qs[(ld4 + 1) * 64 + row] = qv.y * sc;
        Qs[(ld4 + 2) * 64 + row] = qv.z * sc;
        Qs[(ld4 + 3) * 64 + row] = qv.w * sc;
    }

    float mrow[4], lrow[4], oacc[4][8];
#pragma unroll
    for (int i = 0; i < 4; i++) {
        mrow[i] = -1e30f; lrow[i] = 0.f;
#pragma unroll
        for (int c = 0; c < 8; c++) oacc[i][c] = 0.f;
    }

    for (int kt = 0; kt <= (int)blockIdx.x; ++kt) {
        __syncthreads();  // protect Ks/Vs/Ps from previous iteration readers
        const int kc0 = kt * FBN;
#pragma unroll
        for (int j = 0; j < 8; ++j) {
            int row = lr + j * 8;
            float4 kv = *(const float4*)&k[(size_t)(kc0 + row) * DMODEL + hoff + ld4];
            Ks[(ld4 + 0) * 64 + row] = kv.x;
            Ks[(ld4 + 1) * 64 + row] = kv.y;
            Ks[(ld4 + 2) * 64 + row] = kv.z;
            Ks[(ld4 + 3) * 64 + row] = kv.w;
            float4 vv = *(const float4*)&v[(size_t)(kc0 + row) * DMODEL + hoff + ld4];
            *(float4*)&Vs[row * 128 + ld4] = vv;
        }
        __syncthreads();

        float s4[4][4];
#pragma unroll
        for (int i = 0; i < 4; i++)
#pragma unroll
            for (int j = 0; j < 4; j++) s4[i][j] = 0.f;

#pragma unroll 4
        for (int d = 0; d < DHEAD; ++d) {
            float4 qa = *(const float4*)&Qs[d * 64 + ty * 4];
            float4 ka = *(const float4*)&Ks[d * 64 + tx * 4];
            float qv[4] = {qa.x, qa.y, qa.z, qa.w};
            float kv[4] = {ka.x, ka.y, ka.z, ka.w};
#pragma unroll
            for (int i = 0; i < 4; i++)
#pragma unroll
                for (int j = 0; j < 4; j++) s4[i][j] += qv[i] * kv[j];
        }

        const bool diag = (kt == (int)blockIdx.x);
        int amv[4];
#pragma unroll
        for (int j = 0; j < 4; j++) amv[j] = am[kc0 + tx * 4 + j];
#pragma unroll
        for (int i = 0; i < 4; i++) {
            int qrow = q0 + ty * 4 + i;
#pragma unroll
            for (int j = 0; j < 4; j++) {
                int kcol = kc0 + tx * 4 + j;
                bool ok = (amv[j] != 0) && (!diag || (kcol <= qrow));
                if (!ok) s4[i][j] = -1e30f;
            }
        }

#pragma unroll
        for (int i = 0; i < 4; i++) {
            float mx = fmaxf(fmaxf(s4[i][0], s4[i][1]), fmaxf(s4[i][2], s4[i][3]));
            mx = fmaxf(mx, __shfl_xor_sync(0xffffffffu, mx, 1));
            mx = fmaxf(mx, __shfl_xor_sync(0xffffffffu, mx, 2));
            mx = fmaxf(mx, __shfl_xor_sync(0xffffffffu, mx, 4));
            mx = fmaxf(mx, __shfl_xor_sync(0xffffffffu, mx, 8));
            float mnew = fmaxf(mrow[i], mx);
            float alpha = __expf(mrow[i] - mnew);
            float ps = 0.f;
#pragma unroll
            for (int j = 0; j < 4; j++) {
                float p = __expf(s4[i][j] - mnew);
                Ps[(ty * 4 + i) * PSTRIDE + tx * 4 + j] = p;
                ps += p;
            }
            ps += __shfl_xor_sync(0xffffffffu, ps, 1);
            ps += __shfl_xor_sync(0xffffffffu, ps, 2);
            ps += __shfl_xor_sync(0xffffffffu, ps, 4);
            ps += __shfl_xor_sync(0xffffffffu, ps, 8);
            lrow[i] = lrow[i] * alpha + ps;
            mrow[i] = mnew;
#pragma unroll
            for (int c = 0; c < 8; c++) oacc[i][c] *= alpha;
        }
        __syncthreads();

#pragma unroll 2
        for (int kk = 0; kk < FBN; ++kk) {
            float4 va = *(const float4*)&Vs[kk * 128 + tx * 8];
            float4 vb = *(const float4*)&Vs[kk * 128 + tx * 8 + 4];
            float vv[8] = {va.x, va.y, va.z, va.w, vb.x, vb.y, vb.z, vb.w};
#pragma unroll
            for (int i = 0; i < 4; i++) {
                float p = Ps[(ty * 4 + i) * PSTRIDE + kk];
#pragma unroll
                for (int c = 0; c < 8; c++) oacc[i][c] += p * vv[c];
            }
        }
    }

#pragma unroll
    for (int i = 0; i < 4; i++) {
        int qrow = q0 + ty * 4 + i;
        float inv = (am[qrow] != 0) ? (1.f / lrow[i]) : 0.f;
        float4 w0 = make_float4(oacc[i][0] * inv, oacc[i][1] * inv,
                                oacc[i][2] * inv, oacc[i][3] * inv);
        float4 w1 = make_float4(oacc[i][4] * inv, oacc[i][5] * inv,
                                oacc[i][6] * inv, oacc[i][7] * inv);
        *(float4*)&o[(size_t)qrow * DMODEL + hoff + tx * 8]     = w0;
        *(float4*)&o[(size_t)qrow * DMODEL + hoff + tx * 8 + 4] = w1;
    }
}

// ---------------- launch ----------------
extern "C" void kernel_launch(void* const* d_in, const int* in_sizes, int n_in,
                              void* d_out, int out_size) {
    (void)in_sizes; (void)n_in; (void)out_size;
    const float* x    = (const float*)d_in[0];
    const float* cosb = (const float*)d_in[1];
    const float* sinb = (const float*)d_in[2];
    const int*   am   = (const int*)  d_in[3];
    const float* lnw  = (const float*)d_in[4];
    const float* Wq   = (const float*)d_in[5];
    const float* Wk   = (const float*)d_in[6];
    const float* Wv   = (const float*)d_in[7];
    const float* Wo   = (const float*)d_in[8];
    float* out = (float*)d_out;

    float *ph, *pq, *pk, *pv, *pattn;
    cudaGetSymbolAddress((void**)&ph,    g_h);
    cudaGetSymbolAddress((void**)&pq,    g_q);
    cudaGetSymbolAddress((void**)&pk,    g_k);
    cudaGetSymbolAddress((void**)&pv,    g_v);
    cudaGetSymbolAddress((void**)&pattn, g_attn);

    cudaFuncSetAttribute(flash_attn, cudaFuncAttributeMaxDynamicSharedMemorySize,
                         FLASH_SMEM);

    rmsnorm_kernel<<<SEQ, 256>>>(x, lnw, ph);

    dim3 gg(DMODEL / GBM, SEQ / GBM);
    sgemm_nt<<<gg, 256>>>(ph, Wq, pq, nullptr);
    sgemm_nt<<<gg, 256>>>(ph, Wk, pk, nullptr);
    sgemm_nt<<<gg, 256>>>(ph, Wv, pv, nullptr);

    rope_kernel<<<(SEQ * NHEAD * 64) / 256, 256>>>(pq, pk, cosb, sinb);

    dim3 fg(SEQ / FBM, NHEAD);
    flash_attn<<<fg, 256, FLASH_SMEM>>>(pq, pk, pv, am, pattn);

    sgemm_nt<<<gg, 256>>>(pattn, Wo, out, x);
}

// round 8
// speedup vs baseline: 1.3318x; 1.3318x over previous
#include <cuda_runtime.h>
#include <cuda_bf16.h>
#include <cstdint>

// Problem constants
static constexpr int SEQ    = 2048;
static constexpr int DMODEL = 2048;
static constexpr int NHEAD  = 16;
static constexpr int DHEAD  = 128;
static constexpr float EPSV = 1e-5f;

typedef unsigned long long ull;

// ---------------- scratch (device globals; no allocation allowed) ----------------
__device__ __nv_bfloat16 g_hhi[SEQ * DMODEL], g_hlo[SEQ * DMODEL];
__device__ __nv_bfloat16 g_ahi[SEQ * DMODEL], g_alo[SEQ * DMODEL];
__device__ __nv_bfloat16 g_wqhi[DMODEL * DMODEL], g_wqlo[DMODEL * DMODEL];
__device__ __nv_bfloat16 g_wkhi[DMODEL * DMODEL], g_wklo[DMODEL * DMODEL];
__device__ __nv_bfloat16 g_wvhi[DMODEL * DMODEL], g_wvlo[DMODEL * DMODEL];
__device__ __nv_bfloat16 g_wohi[DMODEL * DMODEL], g_wolo[DMODEL * DMODEL];
__device__ float g_q[SEQ * DMODEL];
__device__ float g_k[SEQ * DMODEL];
__device__ float g_v[SEQ * DMODEL];
__device__ float g_attn[SEQ * DMODEL];

// ---------------- low-level helpers (base-target only: no tcgen05) ----------------
__device__ __forceinline__ uint32_t smem_u32(const void* p) {
    uint32_t a;
    asm("{ .reg .u64 t; cvta.to.shared.u64 t, %1; cvt.u32.u64 %0, t; }"
        : "=r"(a) : "l"(p));
    return a;
}
__device__ __forceinline__ ull pack2(float lo, float hi) {
    ull r; asm("mov.b64 %0, {%1, %2};" : "=l"(r) : "f"(lo), "f"(hi)); return r;
}
__device__ __forceinline__ void unpack2(ull v, float& lo, float& hi) {
    asm("mov.b64 {%0, %1}, %2;" : "=f"(lo), "=f"(hi) : "l"(v));
}
__device__ __forceinline__ ull fma2(ull a, ull b, ull c) {
    ull d; asm("fma.rn.f32x2 %0, %1, %2, %3;" : "=l"(d) : "l"(a), "l"(b), "l"(c));
    return d;
}
__device__ __forceinline__ ull mul2(ull a, ull b) {
    ull d; asm("mul.rn.f32x2 %0, %1, %2;" : "=l"(d) : "l"(a), "l"(b));
    return d;
}
__device__ __forceinline__ void cpasync16(uint32_t saddr, const void* gaddr) {
    asm volatile("cp.async.cg.shared.global [%0], [%1], 16;"
                 :: "r"(saddr), "l"(gaddr) : "memory");
}
#define CPASYNC_COMMIT() asm volatile("cp.async.commit_group;" ::: "memory")
#define CPASYNC_WAIT(n)  asm volatile("cp.async.wait_group %0;" :: "n"(n) : "memory")

__device__ __forceinline__ void ldsm4(uint32_t* r, uint32_t addr) {
    asm volatile("ldmatrix.sync.aligned.m8n8.x4.shared.b16 {%0,%1,%2,%3}, [%4];"
                 : "=r"(r[0]), "=r"(r[1]), "=r"(r[2]), "=r"(r[3]) : "r"(addr));
}
// D(16x8,f32) += A(16x16,bf16,row) * B(16x8,bf16,col)
__device__ __forceinline__ void mma16816(float* d, const uint32_t* a, const uint32_t* b) {
    asm volatile(
        "mma.sync.aligned.m16n8k16.row.col.f32.bf16.bf16.f32 "
        "{%0,%1,%2,%3}, {%4,%5,%6,%7}, {%8,%9}, {%0,%1,%2,%3};"
        : "+f"(d[0]), "+f"(d[1]), "+f"(d[2]), "+f"(d[3])
        : "r"(a[0]), "r"(a[1]), "r"(a[2]), "r"(a[3]), "r"(b[0]), "r"(b[1]));
}

// ---------------- hi/lo split ----------------
__device__ __forceinline__ void split1(float x, __nv_bfloat16& hi, __nv_bfloat16& lo) {
    hi = __float2bfloat16_rn(x);
    lo = __float2bfloat16_rn(x - __bfloat162float(hi));
}

__global__ __launch_bounds__(256)
void split_kernel(const float* __restrict__ src, __nv_bfloat16* __restrict__ hi,
                  __nv_bfloat16* __restrict__ lo) {
    int i = (blockIdx.x * 256 + threadIdx.x) * 4;
    float4 v = *(const float4*)&src[i];
    __nv_bfloat16 h0, h1, h2, h3, l0, l1, l2, l3;
    split1(v.x, h0, l0); split1(v.y, h1, l1);
    split1(v.z, h2, l2); split1(v.w, h3, l3);
    *(__nv_bfloat162*)&hi[i]     = __halves2bfloat162(h0, h1);
    *(__nv_bfloat162*)&hi[i + 2] = __halves2bfloat162(h2, h3);
    *(__nv_bfloat162*)&lo[i]     = __halves2bfloat162(l0, l1);
    *(__nv_bfloat162*)&lo[i + 2] = __halves2bfloat162(l2, l3);
}

// ---------------- RMSNorm -> hi/lo bf16 ----------------
__global__ __launch_bounds__(256)
void rmsnorm_split(const float* __restrict__ x, const float* __restrict__ w,
                   __nv_bfloat16* __restrict__ hhi, __nv_bfloat16* __restrict__ hlo) {
    int row = blockIdx.x;
    const float* xr = x + (size_t)row * DMODEL;
    float s = 0.f;
    for (int i = threadIdx.x; i < DMODEL; i += 256) { float v = xr[i]; s += v * v; }
    s += __shfl_xor_sync(0xffffffffu, s, 16);
    s += __shfl_xor_sync(0xffffffffu, s, 8);
    s += __shfl_xor_sync(0xffffffffu, s, 4);
    s += __shfl_xor_sync(0xffffffffu, s, 2);
    s += __shfl_xor_sync(0xffffffffu, s, 1);
    __shared__ float red[8];
    if ((threadIdx.x & 31) == 0) red[threadIdx.x >> 5] = s;
    __syncthreads();
    if (threadIdx.x < 32) {
        float t = (threadIdx.x < 8) ? red[threadIdx.x] : 0.f;
        t += __shfl_xor_sync(0xffffffffu, t, 4);
        t += __shfl_xor_sync(0xffffffffu, t, 2);
        t += __shfl_xor_sync(0xffffffffu, t, 1);
        if (threadIdx.x == 0) red[0] = t;
    }
    __syncthreads();
    float r = rsqrtf(red[0] / (float)DMODEL + EPSV);
    size_t base = (size_t)row * DMODEL;
    for (int i = threadIdx.x; i < DMODEL; i += 256) {
        float y = w[i] * xr[i] * r;
        __nv_bfloat16 h, l;
        split1(y, h, l);
        hhi[base + i] = h;
        hlo[base + i] = l;
    }
}

// ---------------- mma.sync GEMM: C[M,N] = A[M,K] @ B[N,K]^T (+resid) ----------------
// fp32 via bf16 hi/lo 3-term split. CTA 128x128, BK=32, 8 warps (4m x 2n).
// smem stage: Ahi|Alo|Bhi|Blo, each 128 rows x 40 bf16 (80B stride: 16B-aligned,
// conflict-free ldmatrix: bank phases r*20 mod 32 all distinct). Stage=40960B, x2 buf.
static constexpr int GSTRIDE = 40;       // bf16 elems per smem row
static constexpr int TILE_B  = 128 * GSTRIDE * 2;  // 10240 bytes per tile
static constexpr int STAGE_B = 4 * TILE_B;         // 40960
static constexpr int GEMM_SMEM = 2 * STAGE_B;      // 81920
static constexpr int NKT = DMODEL / 32;  // 64

__global__ __launch_bounds__(256, 1)
void gemm_mma(const __nv_bfloat16* __restrict__ Ah, const __nv_bfloat16* __restrict__ Al,
              const __nv_bfloat16* __restrict__ Bh, const __nv_bfloat16* __restrict__ Bl,
              float* __restrict__ C, const float* __restrict__ resid) {
    extern __shared__ __align__(128) char smem[];
    const uint32_t sb = smem_u32(smem);
    const int tid = threadIdx.x, wid = tid >> 5, lane = tid & 31;
    const int wm = wid & 3, wn = wid >> 2;
    const int m0 = blockIdx.y * 128;
    const int n0 = blockIdx.x * 128;

    float acc[2][8][4];
#pragma unroll
    for (int mt = 0; mt < 2; ++mt)
#pragma unroll
        for (int nt = 0; nt < 8; ++nt)
#pragma unroll
            for (int c = 0; c < 4; ++c) acc[mt][nt][c] = 0.f;

    auto issue = [&](int kt, uint32_t buf) {
#pragma unroll
        for (int it = 0; it < 2; ++it) {
            int idx = tid + it * 256;
            int row = idx >> 2, kc = (idx & 3) << 3;
            uint32_t so = (uint32_t)(row * (GSTRIDE * 2) + kc * 2);
            size_t gA = (size_t)(m0 + row) * DMODEL + kt * 32 + kc;
            size_t gB = (size_t)(n0 + row) * DMODEL + kt * 32 + kc;
            cpasync16(buf + so,              Ah + gA);
            cpasync16(buf + TILE_B + so,     Al + gA);
            cpasync16(buf + 2 * TILE_B + so, Bh + gB);
            cpasync16(buf + 3 * TILE_B + so, Bl + gB);
        }
    };

    const int g = lane >> 3, r = lane & 7;
    const int aRow = r + (g & 1) * 8, aK = (g >> 1) * 8;   // A frag lane addressing
    const int bN   = r + (g >> 1) * 8, bK = (g & 1) * 8;   // B frag lane addressing

    issue(0, sb);
    CPASYNC_COMMIT();

    int s = 0;
    for (int kt = 0; kt < NKT; ++kt) {
        const uint32_t buf = sb + s * STAGE_B;
        if (kt + 1 < NKT) {
            issue(kt + 1, sb + (s ^ 1) * STAGE_B);
            CPASYNC_COMMIT();
            CPASYNC_WAIT(1);   // buffer `s` ready; kt+1 still in flight
        } else {
            CPASYNC_WAIT(0);
        }
        __syncthreads();

#pragma unroll
        for (int ks = 0; ks < 2; ++ks) {
            const int kb = ks * 16;
            uint32_t afh[2][4], afl[2][4];
#pragma unroll
            for (int mt = 0; mt < 2; ++mt) {
                int row = wm * 32 + mt * 16 + aRow;
                uint32_t ad = buf + (uint32_t)(row * GSTRIDE + kb + aK) * 2;
                ldsm4(afh[mt], ad);
                ldsm4(afl[mt], ad + TILE_B);
            }
#pragma unroll
            for (int ng = 0; ng < 4; ++ng) {
                int n = wn * 64 + ng * 16 + bN;
                uint32_t bd = buf + 2 * TILE_B + (uint32_t)(n * GSTRIDE + kb + bK) * 2;
                uint32_t bfh[4], bfl[4];
                ldsm4(bfh, bd);
                ldsm4(bfl, bd + TILE_B);
#pragma unroll
                for (int mt = 0; mt < 2; ++mt) {
                    int nt = ng * 2;
                    mma16816(acc[mt][nt],     afh[mt], bfh);      // hi*hi
                    mma16816(acc[mt][nt],     afh[mt], bfl);      // hi*lo
                    mma16816(acc[mt][nt],     afl[mt], bfh);      // lo*hi
                    mma16816(acc[mt][nt + 1], afh[mt], bfh + 2);
                    mma16816(acc[mt][nt + 1], afh[mt], bfl + 2);
                    mma16816(acc[mt][nt + 1], afl[mt], bfh + 2);
                }
            }
        }
        __syncthreads();  // all warps done reading buf before it is overwritten
        s ^= 1;
    }

    // Epilogue: direct register->gmem (float2 per n8 tile row)
#pragma unroll
    for (int mt = 0; mt < 2; ++mt) {
        int row = m0 + wm * 32 + mt * 16 + (lane >> 2);
#pragma unroll
        for (int nt = 0; nt < 8; ++nt) {
            int col = n0 + wn * 64 + nt * 8 + (lane & 3) * 2;
            size_t o0 = (size_t)row * DMODEL + col;
            size_t o1 = o0 + 8 * DMODEL;
            float2 v0 = make_float2(acc[mt][nt][0], acc[mt][nt][1]);
            float2 v1 = make_float2(acc[mt][nt][2], acc[mt][nt][3]);
            if (resid) {
                float2 r0 = *(const float2*)&resid[o0];
                float2 r1 = *(const float2*)&resid[o1];
                v0.x += r0.x; v0.y += r0.y;
                v1.x += r1.x; v1.y += r1.y;
            }
            *(float2*)&C[o0] = v0;
            *(float2*)&C[o1] = v1;
        }
    }
}

// ---------------- RoPE (in-place on Q and K) ----------------
__global__ __launch_bounds__(256)
void rope_kernel(float* __restrict__ q, float* __restrict__ k,
                 const float* __restrict__ cosb, const float* __restrict__ sinb) {
    int i = blockIdx.x * blockDim.x + threadIdx.x;  // over SEQ*NHEAD*64
    if (i >= SEQ * NHEAD * 64) return;
    int d = i & 63;
    int h = (i >> 6) & (NHEAD - 1);
    int t = i >> 10;
    size_t base = (size_t)t * DMODEL + h * DHEAD;
    float c1 = cosb[t * DHEAD + d];
    float s1 = sinb[t * DHEAD + d];
    float c2 = cosb[t * DHEAD + d + 64];
    float s2 = sinb[t * DHEAD + d + 64];
    float a = q[base + d], b = q[base + d + 64];
    q[base + d]      = a * c1 - b * s1;
    q[base + d + 64] = b * c2 + a * s2;
    a = k[base + d]; b = k[base + d + 64];
    k[base + d]      = a * c1 - b * s1;
    k[base + d + 64] = b * c2 + a * s2;
}

// ---------------- Flash attention (fp32, online softmax, f32x2-packed math) ----------
static constexpr int FBM = 64;
static constexpr int FBN = 64;
static constexpr int PSTRIDE = 68;
static constexpr int FLASH_SMEM = (3 * 128 * 64 + 64 * PSTRIDE) * 4;  // 115712 B

__global__ __launch_bounds__(256, 1)
void flash_attn(const float* __restrict__ q, const float* __restrict__ k,
                const float* __restrict__ v, const int* __restrict__ am,
                float* __restrict__ o) {
    extern __shared__ __align__(16) float sm[];
    float* Qs = sm;                // [128][64]  Qs[d][r], pre-scaled
    float* Ks = sm + 128 * 64;     // [128][64]  Ks[d][c]
    float* Vs = sm + 2 * 128 * 64; // [64][128]  Vs[kr][d]
    float* Ps = sm + 3 * 128 * 64; // [64][PSTRIDE]

    const int tid = threadIdx.x;
    const int ty = tid >> 4, tx = tid & 15;
    const int q0 = blockIdx.x * FBM;
    const int hoff = blockIdx.y * DHEAD;
    const float sc = 0.08838834764831845f;  // 1/sqrt(128)

    const int lr  = tid >> 5;
    const int ld4 = (tid & 31) << 2;

#pragma unroll
    for (int j = 0; j < 8; ++j) {
        int row = lr + j * 8;
        float4 qv = *(const float4*)&q[(size_t)(q0 + row) * DMODEL + hoff + ld4];
        Qs[(ld4 + 0) * 64 + row] = qv.x * sc;
        Qs[(ld4 + 1) * 64 + row] = qv.y * sc;
        Qs[(ld4 + 2) * 64 + row] = qv.z * sc;
        Qs[(ld4 + 3) * 64 + row] = qv.w * sc;
    }

    float mrow[4], lrow[4];
    ull op[4][4];  // packed output accumulators (8 floats per row as 4 f32x2)
#pragma unroll
    for (int i = 0; i < 4; i++) {
        mrow[i] = -1e30f; lrow[i] = 0.f;
#pragma unroll
        for (int c = 0; c < 4; c++) op[i][c] = 0ull;
    }

    for (int kt = 0; kt <= (int)blockIdx.x; ++kt) {
        __syncthreads();
        const int kc0 = kt * FBN;
#pragma unroll
        for (int j = 0; j < 8; ++j) {
            int row = lr + j * 8;
            float4 kv = *(const float4*)&k[(size_t)(kc0 + row) * DMODEL + hoff + ld4];
            Ks[(ld4 + 0) * 64 + row] = kv.x;
            Ks[(ld4 + 1) * 64 + row] = kv.y;
            Ks[(ld4 + 2) * 64 + row] = kv.z;
            Ks[(ld4 + 3) * 64 + row] = kv.w;
            float4 vv = *(const float4*)&v[(size_t)(kc0 + row) * DMODEL + hoff + ld4];
            *(float4*)&Vs[row * 128 + ld4] = vv;
        }
        __syncthreads();

        // QK^T: packed f32x2 accumulation (2 k-cols per fma2)
        ull sp[4][2];
#pragma unroll
        for (int i = 0; i < 4; i++) { sp[i][0] = 0ull; sp[i][1] = 0ull; }

#pragma unroll 4
        for (int d = 0; d < DHEAD; ++d) {
            float4 qa = *(const float4*)&Qs[d * 64 + ty * 4];
            float4 ka = *(const float4*)&Ks[d * 64 + tx * 4];
            ull kp0 = pack2(ka.x, ka.y), kp1 = pack2(ka.z, ka.w);
            ull qd;
            qd = pack2(qa.x, qa.x);
            sp[0][0] = fma2(qd, kp0, sp[0][0]); sp[0][1] = fma2(qd, kp1, sp[0][1]);
            qd = pack2(qa.y, qa.y);
            sp[1][0] = fma2(qd, kp0, sp[1][0]); sp[1][1] = fma2(qd, kp1, sp[1][1]);
            qd = pack2(qa.z, qa.z);
            sp[2][0] = fma2(qd, kp0, sp[2][0]); sp[2][1] = fma2(qd, kp1, sp[2][1]);
            qd = pack2(qa.w, qa.w);
            sp[3][0] = fma2(qd, kp0, sp[3][0]); sp[3][1] = fma2(qd, kp1, sp[3][1]);
        }

        float s4[4][4];
#pragma unroll
        for (int i = 0; i < 4; i++) {
            unpack2(sp[i][0], s4[i][0], s4[i][1]);
            unpack2(sp[i][1], s4[i][2], s4[i][3]);
        }

        const bool diag = (kt == (int)blockIdx.x);
        int amv[4];
#pragma unroll
        for (int j = 0; j < 4; j++) amv[j] = am[kc0 + tx * 4 + j];
#pragma unroll
        for (int i = 0; i < 4; i++) {
            int qrow = q0 + ty * 4 + i;
#pragma unroll
            for (int j = 0; j < 4; j++) {
                int kcol = kc0 + tx * 4 + j;
                bool ok = (amv[j] != 0) && (!diag || (kcol <= qrow));
                if (!ok) s4[i][j] = -1e30f;
            }
        }

#pragma unroll
        for (int i = 0; i < 4; i++) {
            float mx = fmaxf(fmaxf(s4[i][0], s4[i][1]), fmaxf(s4[i][2], s4[i][3]));
            mx = fmaxf(mx, __shfl_xor_sync(0xffffffffu, mx, 1));
            mx = fmaxf(mx, __shfl_xor_sync(0xffffffffu, mx, 2));
            mx = fmaxf(mx, __shfl_xor_sync(0xffffffffu, mx, 4));
            mx = fmaxf(mx, __shfl_xor_sync(0xffffffffu, mx, 8));
            float mnew = fmaxf(mrow[i], mx);
            float alpha = __expf(mrow[i] - mnew);
            float ps = 0.f;
#pragma unroll
            for (int j = 0; j < 4; j++) {
                float p = __expf(s4[i][j] - mnew);
                Ps[(ty * 4 + i) * PSTRIDE + tx * 4 + j] = p;
                ps += p;
            }
            ps += __shfl_xor_sync(0xffffffffu, ps, 1);
            ps += __shfl_xor_sync(0xffffffffu, ps, 2);
            ps += __shfl_xor_sync(0xffffffffu, ps, 4);
            ps += __shfl_xor_sync(0xffffffffu, ps, 8);
            lrow[i] = lrow[i] * alpha + ps;
            mrow[i] = mnew;
            ull ap = pack2(alpha, alpha);
#pragma unroll
            for (int c = 0; c < 4; c++) op[i][c] = mul2(op[i][c], ap);
        }
        __syncthreads();

        // P @ V: packed f32x2 accumulation (2 d-cols per fma2)
#pragma unroll 2
        for (int kk = 0; kk < FBN; ++kk) {
            float4 va = *(const float4*)&Vs[kk * 128 + tx * 8];
            float4 vb = *(const float4*)&Vs[kk * 128 + tx * 8 + 4];
            ull vp0 = pack2(va.x, va.y), vp1 = pack2(va.z, va.w);
            ull vp2 = pack2(vb.x, vb.y), vp3 = pack2(vb.z, vb.w);
#pragma unroll
            for (int i = 0; i < 4; i++) {
                float p = Ps[(ty * 4 + i) * PSTRIDE + kk];
                ull pp = pack2(p, p);
                op[i][0] = fma2(pp, vp0, op[i][0]);
                op[i][1] = fma2(pp, vp1, op[i][1]);
                op[i][2] = fma2(pp, vp2, op[i][2]);
                op[i][3] = fma2(pp, vp3, op[i][3]);
            }
        }
    }

#pragma unroll
    for (int i = 0; i < 4; i++) {
        int qrow = q0 + ty * 4 + i;
        float inv = (am[qrow] != 0) ? (1.f / lrow[i]) : 0.f;
        float oa[8];
        unpack2(op[i][0], oa[0], oa[1]);
        unpack2(op[i][1], oa[2], oa[3]);
        unpack2(op[i][2], oa[4], oa[5]);
        unpack2(op[i][3], oa[6], oa[7]);
        float4 w0 = make_float4(oa[0] * inv, oa[1] * inv, oa[2] * inv, oa[3] * inv);
        float4 w1 = make_float4(oa[4] * inv, oa[5] * inv, oa[6] * inv, oa[7] * inv);
        *(float4*)&o[(size_t)qrow * DMODEL + hoff + tx * 8]     = w0;
        *(float4*)&o[(size_t)qrow * DMODEL + hoff + tx * 8 + 4] = w1;
    }
}

// ---------------- launch ----------------
extern "C" void kernel_launch(void* const* d_in, const int* in_sizes, int n_in,
                              void* d_out, int out_size) {
    (void)in_sizes; (void)n_in; (void)out_size;
    const float* x    = (const float*)d_in[0];
    const float* cosb = (const float*)d_in[1];
    const float* sinb = (const float*)d_in[2];
    const int*   am   = (const int*)  d_in[3];
    const float* lnw  = (const float*)d_in[4];
    const float* Wq   = (const float*)d_in[5];
    const float* Wk   = (const float*)d_in[6];
    const float* Wv   = (const float*)d_in[7];
    const float* Wo   = (const float*)d_in[8];
    float* out = (float*)d_out;

    __nv_bfloat16 *hhi, *hlo, *ahi, *alo;
    __nv_bfloat16 *wqh, *wql, *wkh, *wkl, *wvh, *wvl, *woh, *wol;
    float *pq, *pk, *pv, *pattn;
    cudaGetSymbolAddress((void**)&hhi, g_hhi);  cudaGetSymbolAddress((void**)&hlo, g_hlo);
    cudaGetSymbolAddress((void**)&ahi, g_ahi);  cudaGetSymbolAddress((void**)&alo, g_alo);
    cudaGetSymbolAddress((void**)&wqh, g_wqhi); cudaGetSymbolAddress((void**)&wql, g_wqlo);
    cudaGetSymbolAddress((void**)&wkh, g_wkhi); cudaGetSymbolAddress((void**)&wkl, g_wklo);
    cudaGetSymbolAddress((void**)&wvh, g_wvhi); cudaGetSymbolAddress((void**)&wvl, g_wvlo);
    cudaGetSymbolAddress((void**)&woh, g_wohi); cudaGetSymbolAddress((void**)&wol, g_wolo);
    cudaGetSymbolAddress((void**)&pq, g_q);     cudaGetSymbolAddress((void**)&pk, g_k);
    cudaGetSymbolAddress((void**)&pv, g_v);     cudaGetSymbolAddress((void**)&pattn, g_attn);

    cudaFuncSetAttribute(gemm_mma, cudaFuncAttributeMaxDynamicSharedMemorySize, GEMM_SMEM);
    cudaFuncSetAttribute(flash_attn, cudaFuncAttributeMaxDynamicSharedMemorySize, FLASH_SMEM);

    const int split_blocks = (DMODEL * DMODEL) / (256 * 4);  // 4096
    split_kernel<<<split_blocks, 256>>>(Wq, wqh, wql);
    split_kernel<<<split_blocks, 256>>>(Wk, wkh, wkl);
    split_kernel<<<split_blocks, 256>>>(Wv, wvh, wvl);
    split_kernel<<<split_blocks, 256>>>(Wo, woh, wol);

    rmsnorm_split<<<SEQ, 256>>>(x, lnw, hhi, hlo);

    dim3 gg(DMODEL / 128, SEQ / 128);  // (16, 16) = 256 CTAs
    gemm_mma<<<gg, 256, GEMM_SMEM>>>(hhi, hlo, wqh, wql, pq, nullptr);
    gemm_mma<<<gg, 256, GEMM_SMEM>>>(hhi, hlo, wkh, wkl, pk, nullptr);
    gemm_mma<<<gg, 256, GEMM_SMEM>>>(hhi, hlo, wvh, wvl, pv, nullptr);

    rope_kernel<<<(SEQ * NHEAD * 64) / 256, 256>>>(pq, pk, cosb, sinb);

    dim3 fg(SEQ / FBM, NHEAD);
    flash_attn<<<fg, 256, FLASH_SMEM>>>(pq, pk, pv, am, pattn);

    split_kernel<<<(SEQ * DMODEL) / (256 * 4), 256>>>(pattn, ahi, alo);
    gemm_mma<<<gg, 256, GEMM_SMEM>>>(ahi, alo, woh, wol, out, x);
}